// round 8
// baseline (speedup 1.0000x reference)
#include <cuda_runtime.h>
#include <cuda_bf16.h>
#include <math.h>

// Problem constants
#define BATCH   8192
#define DIM     1024      // DIM1 == DIM2
#define SKETCH  8192
#define OUT     512
#define LN_EPS  1e-5f

#define MCAP    1024      // |J| <= 1024 (hard bound)
#define MFAST   192       // fast-path bound on |J| (expected ~113)
#define CCH     128       // column chunk for fallback path
#define TB      64        // batch rows per CTA in main kernel
#define NTHR    1024      // threads per CTA (32 warps)
#define SUBCL   8         // W staging sub-chunk (8 cols x 512 = 16KB)
#define XSTRIDE 1025      // padded row stride for xs tile (conflict-free gather)

// dynamic smem layout (floats)
#define SP_OFF   0                         // sp[MFAST*64]      product tile
#define XS_OFF   (MFAST * TB)              // xs[32*XSTRIDE]    staged x rows
#define WS_OFF   (XS_OFF + 32 * XSTRIDE)   // WS[SUBCL*OUT]     W staging
#define DSM_FLOATS (WS_OFF + SUBCL * OUT)
#define DSM_BYTES  (DSM_FLOATS * 4)

// ---------------- device globals (scratch; no cudaMalloc allowed) ----------
__device__ unsigned int g_idx1[DIM];
__device__ unsigned int g_idx2[DIM];
__device__ int          g_m;
__device__ int          g_colJ[MCAP];
__device__ int          g_cp1[MCAP + 1];
__device__ int          g_cp2[MCAP + 1];
__device__ unsigned int g_ent1[MCAP];    // (sign<<15) | i
__device__ unsigned int g_ent2[MCAP];
__device__ float        g_Wc[MCAP * OUT];

// -------- f32x2 packed-FMA helpers (PTX-only) ------------------------------
__device__ __forceinline__ unsigned long long pack2(float lo, float hi) {
    unsigned long long r;
    asm("mov.b64 %0, {%1, %2};" : "=l"(r) : "f"(lo), "f"(hi));
    return r;
}
__device__ __forceinline__ void unpack2(unsigned long long v, float& lo, float& hi) {
    asm("mov.b64 {%0, %1}, %2;" : "=f"(lo), "=f"(hi) : "l"(v));
}
__device__ __forceinline__ unsigned long long ffma2(unsigned long long a,
                                                    unsigned long long b,
                                                    unsigned long long c) {
    unsigned long long d;
    asm("fma.rn.f32x2 %0, %1, %2, %3;" : "=l"(d) : "l"(a), "l"(b), "l"(c));
    return d;
}

// ---------------------------------------------------------------------------
// Kernel A: find the single nonzero per row of S1/S2. Coalesced float4 scan.
// ---------------------------------------------------------------------------
__global__ void k_extract(const float* __restrict__ S1,
                          const float* __restrict__ S2)
{
    int row = blockIdx.x;
    const float* S;
    unsigned int* outp;
    if (row < DIM) { S = S1; outp = g_idx1; }
    else           { S = S2; outp = g_idx2; row -= DIM; }

    const float4* p = (const float4*)(S + (size_t)row * SKETCH);
    int t = threadIdx.x;
#pragma unroll
    for (int k = 0; k < SKETCH / 4 / 256; k++) {
        int v4 = t + k * 256;
        float4 v = p[v4];
        int base = v4 * 4;
        if (v.x != 0.0f) outp[row] = (unsigned)(base + 0) | (v.x < 0.0f ? 0x80000000u : 0u);
        if (v.y != 0.0f) outp[row] = (unsigned)(base + 1) | (v.y < 0.0f ? 0x80000000u : 0u);
        if (v.z != 0.0f) outp[row] = (unsigned)(base + 2) | (v.z < 0.0f ? 0x80000000u : 0u);
        if (v.w != 0.0f) outp[row] = (unsigned)(base + 3) | (v.w < 0.0f ? 0x80000000u : 0u);
    }
}

// ---------------------------------------------------------------------------
// Kernel B: build compact structure + per-column CSR. One CTA, 1024 threads.
// ---------------------------------------------------------------------------
__global__ void k_build()
{
    __shared__ int cnt[SKETCH];
    __shared__ int scanbuf[1024];
    __shared__ int colcnt[MCAP];

    int t = threadIdx.x;

    for (int j = t; j < SKETCH; j += 1024) cnt[j] = 0;
    __syncthreads();

    unsigned u1 = g_idx1[t];
    unsigned u2 = g_idx2[t];
    atomicAdd(&cnt[u1 & (SKETCH - 1)], 1);
    atomicAdd(&cnt[u2 & (SKETCH - 1)], 1 << 16);
    __syncthreads();

    int q = 0;
    int qual[8];
#pragma unroll
    for (int u = 0; u < 8; u++) {
        int j = t * 8 + u;
        int c = cnt[j];
        qual[u] = ((c & 0xFFFF) > 0 && (c >> 16) > 0) ? 1 : 0;
        q += qual[u];
    }
    scanbuf[t] = q;
    __syncthreads();
    for (int off = 1; off < 1024; off <<= 1) {
        int v = (t >= off) ? scanbuf[t - off] : 0;
        __syncthreads();
        scanbuf[t] += v;
        __syncthreads();
    }
    int excl = scanbuf[t] - q;
    int total = scanbuf[1023];

#pragma unroll
    for (int u = 0; u < 8; u++) {
        int j = t * 8 + u;
        if (qual[u]) { g_colJ[excl] = j; cnt[j] = excl; excl++; }
        else         { cnt[j] = -1; }
    }
    if (t == 0) g_m = total;
    __syncthreads();

    int c1 = cnt[u1 & (SKETCH - 1)];
    int c2 = cnt[u2 & (SKETCH - 1)];
#pragma unroll
    for (int s = 0; s < 2; s++) {
        int cc = s ? c2 : c1;
        unsigned uu = s ? u2 : u1;
        int* cp = s ? g_cp2 : g_cp1;
        unsigned int* ent = s ? g_ent2 : g_ent1;

        colcnt[t] = 0;
        __syncthreads();
        if (cc >= 0) atomicAdd(&colcnt[cc], 1);
        __syncthreads();

        int myc = colcnt[t];
        scanbuf[t] = myc;
        __syncthreads();
        for (int off = 1; off < 1024; off <<= 1) {
            int v = (t >= off) ? scanbuf[t - off] : 0;
            __syncthreads();
            scanbuf[t] += v;
            __syncthreads();
        }
        int ex = scanbuf[t] - myc;
        cp[t] = ex;
        if (t == 1023) cp[1024] = scanbuf[1023];
        colcnt[t] = ex;
        __syncthreads();
        if (cc >= 0) {
            int slot = atomicAdd(&colcnt[cc], 1);
            ent[slot] = (((uu >> 31) & 1u) << 15) | (unsigned)t;
        }
        __syncthreads();
    }
}

// ---------------------------------------------------------------------------
// Kernel B2: gather compacted W rows.
// ---------------------------------------------------------------------------
__global__ void k_wgather(const float* __restrict__ W)
{
    int c = blockIdx.x;
    if (c < g_m) {
        g_Wc[(size_t)c * OUT + threadIdx.x] =
            W[(size_t)g_colJ[c] * OUT + threadIdx.x];
    }
}

// ---------------------------------------------------------------------------
// GEMM micro-step: column (base+c2) of vtile (stride TB), W from WS row c2.
// ---------------------------------------------------------------------------
#define GEMM_STEP(vtile, base, c2_)                                            \
    {                                                                          \
        float2 vv = *(const float2*)&(vtile)[((base) + (c2_)) * TB + r0];      \
        unsigned long long v2a = pack2(vv.x, vv.x);                            \
        unsigned long long v2b = pack2(vv.y, vv.y);                            \
        const ulonglong2* wp = (const ulonglong2*)&WS[(c2_) * OUT + o0];       \
        ulonglong2 w01 = wp[0];                                                \
        ulonglong2 w23 = wp[1];                                                \
        ulonglong2 w45 = wp[2];                                                \
        ulonglong2 w67 = wp[3];                                                \
        acc2[0][0] = ffma2(v2a, w01.x, acc2[0][0]);                            \
        acc2[1][0] = ffma2(v2b, w01.x, acc2[1][0]);                            \
        acc2[0][1] = ffma2(v2a, w01.y, acc2[0][1]);                            \
        acc2[1][1] = ffma2(v2b, w01.y, acc2[1][1]);                            \
        acc2[0][2] = ffma2(v2a, w23.x, acc2[0][2]);                            \
        acc2[1][2] = ffma2(v2b, w23.x, acc2[1][2]);                            \
        acc2[0][3] = ffma2(v2a, w23.y, acc2[0][3]);                            \
        acc2[1][3] = ffma2(v2b, w23.y, acc2[1][3]);                            \
        acc2[0][4] = ffma2(v2a, w45.x, acc2[0][4]);                            \
        acc2[1][4] = ffma2(v2b, w45.x, acc2[1][4]);                            \
        acc2[0][5] = ffma2(v2a, w45.y, acc2[0][5]);                            \
        acc2[1][5] = ffma2(v2b, w45.y, acc2[1][5]);                            \
        acc2[0][6] = ffma2(v2a, w67.x, acc2[0][6]);                            \
        acc2[1][6] = ffma2(v2b, w67.x, acc2[1][6]);                            \
        acc2[0][7] = ffma2(v2a, w67.y, acc2[0][7]);                            \
        acc2[1][7] = ffma2(v2b, w67.y, acc2[1][7]);                            \
    }

// ---------------------------------------------------------------------------
// Main fused kernel. TB=64 rows/CTA, 1024 threads (32 warps), 128 CTAs.
//
// FAST PATH (m <= MFAST, expected m~113):
//   For each 32-row half: stage x1 rows into xs (coalesced LDG.128 ->
//   STS.32, stride 1025), CSR-gather s1 from xs (conflict-free LDS: warp =
//   uniform column c, lane = row, bank=(r+i)%32 all distinct), write into
//   sp[c][row]; repeat with x2 and multiply in place. Then ONE GEMM pass
//   over all m columns with W staged per 8-col sub-tile (warp-uniform
//   broadcast LDS.128), fma.rn.f32x2 accumulation.
// FALLBACK (m > MFAST): round-7 chunked path, gathers x from gmem.
// Epilogue: LayerNorm (bias folded into acc init) + ReLU.
// ---------------------------------------------------------------------------
__global__ void __launch_bounds__(NTHR, 1)
k_main(const float* __restrict__ x1, const float* __restrict__ x2,
       const float* __restrict__ bias, const float* __restrict__ gamma,
       const float* __restrict__ beta, float* __restrict__ out)
{
    extern __shared__ __align__(16) float dsm[];
    float* sp = dsm + SP_OFF;     // [MFAST][TB] product tile (fallback: s1c)
    float* xs = dsm + XS_OFF;     // [32][XSTRIDE] staged x rows
    float* WS = dsm + WS_OFF;     // [SUBCL][OUT] W staging

    int tid  = threadIdx.x;
    int lane = tid & 31;
    int wrp  = tid >> 5;          // 0..31 -> cols [wrp*16, wrp*16+16)
    int o0   = wrp * 16;
    int r0   = lane * 2;          // rows r0, r0+1
    int b0   = blockIdx.x * TB;

    int m = g_m;

    // accumulators: acc2[p][k] = row (r0+p), cols (o0+2k, o0+2k+1)
    unsigned long long acc2[2][8];
    {
        const ulonglong2* bq = (const ulonglong2*)(bias + o0);
#pragma unroll
        for (int q = 0; q < 4; q++) {
            ulonglong2 bb = __ldg(bq + q);
            acc2[0][2 * q]     = bb.x;
            acc2[0][2 * q + 1] = bb.y;
            acc2[1][2 * q]     = bb.x;
            acc2[1][2 * q + 1] = bb.y;
        }
    }

    if (m <= MFAST) {
        // ================= FAST PATH =================
        // ---- build product tile sp[m][64] via smem-staged gather ----
#pragma unroll
        for (int rb = 0; rb < 2; rb++) {
            int rbase = rb * 32;

            // stage x1 rows [b0+rbase, +32): coalesced LDG.128 -> STS.32
            for (int q = tid; q < 32 * 256; q += NTHR) {
                int r  = q >> 8;
                int i4 = (q & 255) * 4;
                float4 v = __ldg((const float4*)&x1[(size_t)(b0 + rbase + r) * DIM + i4]);
                float* dst = &xs[r * XSTRIDE + i4];
                dst[0] = v.x; dst[1] = v.y; dst[2] = v.z; dst[3] = v.w;
            }
            __syncthreads();

            // gather s1: warp-uniform c, lane = row -> conflict-free LDS
            for (int p = tid; p < m * 32; p += NTHR) {
                int c = p >> 5;
                int r = p & 31;
                float s = 0.0f;
                int e0 = __ldg(&g_cp1[c]), e1 = __ldg(&g_cp1[c + 1]);
                for (int e = e0; e < e1; e++) {
                    unsigned u = __ldg(&g_ent1[e]);
                    float x = xs[r * XSTRIDE + (u & 1023u)];
                    s += (u & 0x8000u) ? -x : x;
                }
                sp[c * TB + rbase + r] = s;
            }
            __syncthreads();

            // stage x2 rows (reuse xs)
            for (int q = tid; q < 32 * 256; q += NTHR) {
                int r  = q >> 8;
                int i4 = (q & 255) * 4;
                float4 v = __ldg((const float4*)&x2[(size_t)(b0 + rbase + r) * DIM + i4]);
                float* dst = &xs[r * XSTRIDE + i4];
                dst[0] = v.x; dst[1] = v.y; dst[2] = v.z; dst[3] = v.w;
            }
            __syncthreads();

            // gather s2 and multiply in place
            for (int p = tid; p < m * 32; p += NTHR) {
                int c = p >> 5;
                int r = p & 31;
                float s = 0.0f;
                int e0 = __ldg(&g_cp2[c]), e1 = __ldg(&g_cp2[c + 1]);
                for (int e = e0; e < e1; e++) {
                    unsigned u = __ldg(&g_ent2[e]);
                    float x = xs[r * XSTRIDE + (u & 1023u)];
                    s += (u & 0x8000u) ? -x : x;
                }
                sp[c * TB + rbase + r] *= s;
            }
            __syncthreads();
        }

        // ---- one GEMM pass over all m columns ----
        int nsub = (m + SUBCL - 1) / SUBCL;
        for (int sub = 0; sub < nsub; sub++) {
            {   // stage 8 W rows: 1 float4 per thread, coalesced
                int row = tid >> 7;
                int col = (tid & 127) * 4;
                *(float4*)&WS[row * OUT + col] = __ldg(
                    (const float4*)&g_Wc[(size_t)(sub * SUBCL + row) * OUT + col]);
            }
            __syncthreads();

            int base = sub * SUBCL;
            int Csub = min(SUBCL, m - base);
            if (Csub == SUBCL) {
#pragma unroll
                for (int c2 = 0; c2 < SUBCL; c2++) GEMM_STEP(sp, base, c2)
            } else {
                for (int c2 = 0; c2 < Csub; c2++) GEMM_STEP(sp, base, c2)
            }
            __syncthreads();
        }
    } else {
        // ================= FALLBACK (round-7 path) =================
        int nch = (m + CCH - 1) / CCH;
        for (int ch = 0; ch < nch; ch++) {
            int ck0 = ch * CCH;
            int Cn  = min(CCH, m - ck0);
            {
                int nw = Cn * TB;
                for (int p = tid; p < nw; p += NTHR) {
                    int cl = p >> 6;
                    int r  = p & 63;
                    int c  = ck0 + cl;
                    size_t rowoff = (size_t)(b0 + r) * DIM;

                    float s1 = 0.0f;
                    int e0 = __ldg(&g_cp1[c]), e1 = __ldg(&g_cp1[c + 1]);
                    for (int e = e0; e < e1; e++) {
                        unsigned u = __ldg(&g_ent1[e]);
                        float x = __ldg(&x1[rowoff + (u & 1023u)]);
                        s1 += (u & 0x8000u) ? -x : x;
                    }
                    float s2 = 0.0f;
                    int f0 = __ldg(&g_cp2[c]), f1 = __ldg(&g_cp2[c + 1]);
                    for (int e = f0; e < f1; e++) {
                        unsigned u = __ldg(&g_ent2[e]);
                        float x = __ldg(&x2[rowoff + (u & 1023u)]);
                        s2 += (u & 0x8000u) ? -x : x;
                    }
                    sp[cl * TB + r] = s1 * s2;
                }
            }
            __syncthreads();

            int nsub = (Cn + SUBCL - 1) / SUBCL;
            for (int sub = 0; sub < nsub; sub++) {
                {
                    int row = tid >> 7;
                    int col = (tid & 127) * 4;
                    *(float4*)&WS[row * OUT + col] = __ldg(
                        (const float4*)&g_Wc[(size_t)(ck0 + sub * SUBCL + row) * OUT + col]);
                }
                __syncthreads();
                int base = sub * SUBCL;
                int Csub = min(SUBCL, Cn - base);
                if (Csub == SUBCL) {
#pragma unroll
                    for (int c2 = 0; c2 < SUBCL; c2++) GEMM_STEP(sp, base, c2)
                } else {
                    for (int c2 = 0; c2 < Csub; c2++) GEMM_STEP(sp, base, c2)
                }
                __syncthreads();
            }
        }
    }

    // -------- LayerNorm: reduce each row across the 32 warps ---------------
    float* red_s = xs;                   // aliases staged-x buffer
    float* red_q = xs + TB * 33;
#pragma unroll
    for (int p = 0; p < 2; p++) {
        float s = 0.0f, q = 0.0f;
#pragma unroll
        for (int k = 0; k < 8; k++) {
            float lo, hi;
            unpack2(acc2[p][k], lo, hi);
            s += lo + hi;
            q += lo * lo + hi * hi;
        }
        red_s[(r0 + p) * 33 + wrp] = s;
        red_q[(r0 + p) * 33 + wrp] = q;
    }
    __syncthreads();

    float* shmu = WS;                    // aliases W staging buffer
    float* shrs = WS + TB;
    if (tid < TB) {
        float s = 0.0f, q = 0.0f;
#pragma unroll
        for (int w = 0; w < 32; w++) {
            s += red_s[tid * 33 + w];
            q += red_q[tid * 33 + w];
        }
        float mu  = s * (1.0f / OUT);
        float var = q * (1.0f / OUT) - mu * mu;
        shmu[tid] = mu;
        shrs[tid] = rsqrtf(var + LN_EPS);
    }
    __syncthreads();

    // -------- normalize, affine, ReLU, store -------------------------------
#pragma unroll
    for (int p = 0; p < 2; p++) {
        int row = r0 + p;
        float mu = shmu[row];
        float rs = shrs[row];
        float* dst = out + (size_t)(b0 + row) * OUT + o0;
#pragma unroll
        for (int q = 0; q < 4; q++) {
            float4 g4 = __ldg((const float4*)(gamma + o0 + 4 * q));
            float4 e4 = __ldg((const float4*)(beta  + o0 + 4 * q));
            float lo0, hi0, lo1, hi1;
            unpack2(acc2[p][2 * q],     lo0, hi0);
            unpack2(acc2[p][2 * q + 1], lo1, hi1);
            float4 o4;
            o4.x = fmaxf((lo0 - mu) * rs * g4.x + e4.x, 0.0f);
            o4.y = fmaxf((hi0 - mu) * rs * g4.y + e4.y, 0.0f);
            o4.z = fmaxf((lo1 - mu) * rs * g4.z + e4.z, 0.0f);
            o4.w = fmaxf((hi1 - mu) * rs * g4.w + e4.w, 0.0f);
            *(float4*)(dst + 4 * q) = o4;
        }
    }
}

// ---------------------------------------------------------------------------
extern "C" void kernel_launch(void* const* d_in, const int* in_sizes, int n_in,
                              void* d_out, int out_size)
{
    const float* x1    = (const float*)d_in[0];
    const float* x2    = (const float*)d_in[1];
    const float* S1    = (const float*)d_in[2];
    const float* S2    = (const float*)d_in[3];
    const float* W     = (const float*)d_in[4];
    const float* b     = (const float*)d_in[5];
    const float* gamma = (const float*)d_in[6];
    const float* beta  = (const float*)d_in[7];
    float* out = (float*)d_out;

    // allow large dynamic smem (attribute set, not an allocation; idempotent)
    cudaFuncSetAttribute(k_main, cudaFuncAttributeMaxDynamicSharedMemorySize,
                         DSM_BYTES);

    k_extract<<<2 * DIM, 256>>>(S1, S2);
    k_build<<<1, 1024>>>();
    k_wgather<<<MCAP, OUT>>>(W);
    k_main<<<BATCH / TB, NTHR, DSM_BYTES>>>(x1, x2, b, gamma, beta, out);
}

// round 9
// speedup vs baseline: 1.1200x; 1.1200x over previous
#include <cuda_runtime.h>
#include <cuda_bf16.h>
#include <math.h>

// Problem constants
#define BATCH   8192
#define DIM     1024      // DIM1 == DIM2
#define SKETCH  8192
#define OUT     512
#define LN_EPS  1e-5f

#define MCAP    1024      // |J| <= 1024 (hard bound)
#define CCH     128       // column chunk for main kernel
#define TB      64        // batch rows per CTA in main kernel
#define NTHR    1024      // threads per CTA (32 warps)
#define SUBCL   16        // W staging sub-chunk (16 cols x 512 x 4B = 32KB)

// dynamic smem layout (floats): sp[CCH*TB] (32KB) + WS[SUBCL*OUT] (32KB)
#define SP_OFF   0
#define WS_OFF   (CCH * TB)
#define DSM_FLOATS (WS_OFF + SUBCL * OUT)
#define DSM_BYTES  (DSM_FLOATS * 4)

// ---------------- device globals (scratch; no cudaMalloc allowed) ----------
__device__ unsigned int g_idx1[DIM];
__device__ unsigned int g_idx2[DIM];
__device__ int          g_m;
__device__ int          g_fallback;       // 1 if any column has >4 entries
__device__ int          g_colJ[MCAP];
__device__ int          g_cp1[MCAP + 1];
__device__ int          g_cp2[MCAP + 1];
__device__ unsigned int g_ent1[MCAP];     // (sign<<15) | i
__device__ unsigned int g_ent2[MCAP];
__device__ ulonglong2   g_rec[MCAP];      // packed per-column records
__device__ float        g_Wc[MCAP * OUT];

// -------- f32x2 packed-FMA helpers (PTX-only) ------------------------------
__device__ __forceinline__ unsigned long long pack2(float lo, float hi) {
    unsigned long long r;
    asm("mov.b64 %0, {%1, %2};" : "=l"(r) : "f"(lo), "f"(hi));
    return r;
}
__device__ __forceinline__ void unpack2(unsigned long long v, float& lo, float& hi) {
    asm("mov.b64 {%0, %1}, %2;" : "=f"(lo), "=f"(hi) : "l"(v));
}
__device__ __forceinline__ unsigned long long ffma2(unsigned long long a,
                                                    unsigned long long b,
                                                    unsigned long long c) {
    unsigned long long d;
    asm("fma.rn.f32x2 %0, %1, %2, %3;" : "=l"(d) : "l"(a), "l"(b), "l"(c));
    return d;
}
// apply packed sign: e bit10 set -> negate (XOR into fp32 sign bit)
__device__ __forceinline__ float sgnapply(float x, unsigned e) {
    return __int_as_float(__float_as_int(x) ^ (int)((e & 1024u) << 21));
}

// ---------------------------------------------------------------------------
// Kernel A: find the single nonzero per row of S1/S2. Coalesced float4 scan.
// ---------------------------------------------------------------------------
__global__ void k_extract(const float* __restrict__ S1,
                          const float* __restrict__ S2)
{
    int row = blockIdx.x;
    const float* S;
    unsigned int* outp;
    if (row < DIM) { S = S1; outp = g_idx1; }
    else           { S = S2; outp = g_idx2; row -= DIM; }

    const float4* p = (const float4*)(S + (size_t)row * SKETCH);
    int t = threadIdx.x;
#pragma unroll
    for (int k = 0; k < SKETCH / 4 / 256; k++) {
        int v4 = t + k * 256;
        float4 v = p[v4];
        int base = v4 * 4;
        if (v.x != 0.0f) outp[row] = (unsigned)(base + 0) | (v.x < 0.0f ? 0x80000000u : 0u);
        if (v.y != 0.0f) outp[row] = (unsigned)(base + 1) | (v.y < 0.0f ? 0x80000000u : 0u);
        if (v.z != 0.0f) outp[row] = (unsigned)(base + 2) | (v.z < 0.0f ? 0x80000000u : 0u);
        if (v.w != 0.0f) outp[row] = (unsigned)(base + 3) | (v.w < 0.0f ? 0x80000000u : 0u);
    }
}

// ---------------------------------------------------------------------------
// Kernel B: build compact structure + CSR + packed records. 1 CTA, 1024 thr.
// ---------------------------------------------------------------------------
__global__ void k_build()
{
    __shared__ int cnt[SKETCH];
    __shared__ int scanbuf[1024];
    __shared__ int colcnt[MCAP];

    int t = threadIdx.x;

    for (int j = t; j < SKETCH; j += 1024) cnt[j] = 0;
    if (t == 0) g_fallback = 0;
    __syncthreads();

    unsigned u1 = g_idx1[t];
    unsigned u2 = g_idx2[t];
    atomicAdd(&cnt[u1 & (SKETCH - 1)], 1);
    atomicAdd(&cnt[u2 & (SKETCH - 1)], 1 << 16);
    __syncthreads();

    int q = 0;
    int qual[8];
#pragma unroll
    for (int u = 0; u < 8; u++) {
        int j = t * 8 + u;
        int c = cnt[j];
        qual[u] = ((c & 0xFFFF) > 0 && (c >> 16) > 0) ? 1 : 0;
        q += qual[u];
    }
    scanbuf[t] = q;
    __syncthreads();
    for (int off = 1; off < 1024; off <<= 1) {
        int v = (t >= off) ? scanbuf[t - off] : 0;
        __syncthreads();
        scanbuf[t] += v;
        __syncthreads();
    }
    int excl = scanbuf[t] - q;
    int total = scanbuf[1023];

#pragma unroll
    for (int u = 0; u < 8; u++) {
        int j = t * 8 + u;
        if (qual[u]) { g_colJ[excl] = j; cnt[j] = excl; excl++; }
        else         { cnt[j] = -1; }
    }
    if (t == 0) g_m = total;
    __syncthreads();

    int c1 = cnt[u1 & (SKETCH - 1)];
    int c2 = cnt[u2 & (SKETCH - 1)];
#pragma unroll
    for (int s = 0; s < 2; s++) {
        int cc = s ? c2 : c1;
        unsigned uu = s ? u2 : u1;
        int* cp = s ? g_cp2 : g_cp1;
        unsigned int* ent = s ? g_ent2 : g_ent1;

        colcnt[t] = 0;
        __syncthreads();
        if (cc >= 0) atomicAdd(&colcnt[cc], 1);
        __syncthreads();

        int myc = colcnt[t];
        scanbuf[t] = myc;
        __syncthreads();
        for (int off = 1; off < 1024; off <<= 1) {
            int v = (t >= off) ? scanbuf[t - off] : 0;
            __syncthreads();
            scanbuf[t] += v;
            __syncthreads();
        }
        int ex = scanbuf[t] - myc;
        cp[t] = ex;
        if (t == 1023) cp[1024] = scanbuf[1023];
        colcnt[t] = ex;
        __syncthreads();
        if (cc >= 0) {
            int slot = atomicAdd(&colcnt[cc], 1);
            ent[slot] = (((uu >> 31) & 1u) << 15) | (unsigned)t;
        }
        __syncthreads();
    }

    // ---- build packed records: per column, both sides, up to 4 entries ----
    if (t < total) {
        unsigned long long w[2];
#pragma unroll
        for (int s = 0; s < 2; s++) {
            const int* cp = s ? g_cp2 : g_cp1;
            const unsigned int* ent = s ? g_ent2 : g_ent1;
            int e0 = cp[t], e1 = cp[t + 1];
            int cnte = e1 - e0;
            if (cnte > 4) { atomicOr(&g_fallback, 1); cnte = 4; }
            unsigned long long u = 0;
            for (int k = 0; k < cnte; k++) {
                unsigned v = ent[e0 + k];
                unsigned i = v & 1023u;
                unsigned sg = (v >> 15) & 1u;
                u |= (unsigned long long)(i | (sg << 10)) << (11 * k);
            }
            u |= (unsigned long long)cnte << 60;
            w[s] = u;
        }
        ulonglong2 r;
        r.x = w[0];
        r.y = w[1];
        g_rec[t] = r;
    }
}

// ---------------------------------------------------------------------------
// Kernel B2: gather compacted W rows.
// ---------------------------------------------------------------------------
__global__ void k_wgather(const float* __restrict__ W)
{
    int c = blockIdx.x;
    if (c < g_m) {
        g_Wc[(size_t)c * OUT + threadIdx.x] =
            W[(size_t)g_colJ[c] * OUT + threadIdx.x];
    }
}

// ---------------------------------------------------------------------------
// GEMM micro-step (unchanged from round 7 — proven floor-rate inner loop)
// ---------------------------------------------------------------------------
#define GEMM_STEP(vtile, base, c2_)                                            \
    {                                                                          \
        float2 vv = *(const float2*)&(vtile)[((base) + (c2_)) * TB + r0];      \
        unsigned long long v2a = pack2(vv.x, vv.x);                            \
        unsigned long long v2b = pack2(vv.y, vv.y);                            \
        const ulonglong2* wp = (const ulonglong2*)&WS[(c2_) * OUT + o0];       \
        ulonglong2 w01 = wp[0];                                                \
        ulonglong2 w23 = wp[1];                                                \
        ulonglong2 w45 = wp[2];                                                \
        ulonglong2 w67 = wp[3];                                                \
        acc2[0][0] = ffma2(v2a, w01.x, acc2[0][0]);                            \
        acc2[1][0] = ffma2(v2b, w01.x, acc2[1][0]);                            \
        acc2[0][1] = ffma2(v2a, w01.y, acc2[0][1]);                            \
        acc2[1][1] = ffma2(v2b, w01.y, acc2[1][1]);                            \
        acc2[0][2] = ffma2(v2a, w23.x, acc2[0][2]);                            \
        acc2[1][2] = ffma2(v2b, w23.x, acc2[1][2]);                            \
        acc2[0][3] = ffma2(v2a, w23.y, acc2[0][3]);                            \
        acc2[1][3] = ffma2(v2b, w23.y, acc2[1][3]);                            \
        acc2[0][4] = ffma2(v2a, w45.x, acc2[0][4]);                            \
        acc2[1][4] = ffma2(v2b, w45.x, acc2[1][4]);                            \
        acc2[0][5] = ffma2(v2a, w45.y, acc2[0][5]);                            \
        acc2[1][5] = ffma2(v2b, w45.y, acc2[1][5]);                            \
        acc2[0][6] = ffma2(v2a, w67.x, acc2[0][6]);                            \
        acc2[1][6] = ffma2(v2b, w67.x, acc2[1][6]);                            \
        acc2[0][7] = ffma2(v2a, w67.y, acc2[0][7]);                            \
        acc2[1][7] = ffma2(v2b, w67.y, acc2[1][7]);                            \
    }

// ---------------------------------------------------------------------------
// Main fused kernel. TB=64 rows/CTA, 1024 threads (32 warps), 128 CTAs.
//  Gather (fast): per warp-item, column c is uniform; ONE uniform LDG.128
//  yields both sides' packed entries; each thread computes rows r and r+32
//  (2 products per record load). Sign applied by XOR. No pointer loads, no
//  data-dependent inner loops (<=3 extra entries, uniform predicates).
//  Gather (fallback, g_fallback set): round-7 CSR walk.
//  GEMM: W staged to smem per 16-col sub-tile, warp-uniform broadcast LDS,
//  fma.rn.f32x2, warp=16 cols x lane=2 rows.
//  Epilogue: LayerNorm (bias folded into acc init) + ReLU.
// ---------------------------------------------------------------------------
__global__ void __launch_bounds__(NTHR, 1)
k_main(const float* __restrict__ x1, const float* __restrict__ x2,
       const float* __restrict__ bias, const float* __restrict__ gamma,
       const float* __restrict__ beta, float* __restrict__ out)
{
    extern __shared__ __align__(16) float dsm[];
    float* sp = dsm + SP_OFF;     // [CCH][TB] product tile; LN bufs alias
    float* WS = dsm + WS_OFF;     // [SUBCL][OUT] W staging; mu/rs alias

    int tid  = threadIdx.x;
    int lane = tid & 31;
    int wrp  = tid >> 5;          // 0..31 -> cols [wrp*16, wrp*16+16)
    int o0   = wrp * 16;
    int r0   = lane * 2;          // rows r0, r0+1
    int b0   = blockIdx.x * TB;

    int m  = g_m;
    int fb = g_fallback;

    // accumulators: acc2[p][k] = row (r0+p), cols (o0+2k, o0+2k+1)
    unsigned long long acc2[2][8];
    {
        const ulonglong2* bq = (const ulonglong2*)(bias + o0);
#pragma unroll
        for (int q = 0; q < 4; q++) {
            ulonglong2 bb = __ldg(bq + q);
            acc2[0][2 * q]     = bb.x;
            acc2[0][2 * q + 1] = bb.y;
            acc2[1][2 * q]     = bb.x;
            acc2[1][2 * q + 1] = bb.y;
        }
    }

    int nch = (m + CCH - 1) / CCH;
    for (int ch = 0; ch < nch; ch++) {
        int ck0 = ch * CCH;
        int Cn  = min(CCH, m - ck0);

        if (!fb) {
            // ---- fast gather: records, 2 rows per thread ----
            int nw = Cn * 32;
            for (int p = tid; p < nw; p += NTHR) {
                int cl = p >> 5;
                int r  = p & 31;
                int c  = ck0 + cl;
                ulonglong2 rec = __ldg(&g_rec[c]);
                size_t ro0 = (size_t)(b0 + r) * DIM;
                size_t ro1 = (size_t)(b0 + r + 32) * DIM;

                // side 1
                unsigned long long u = rec.x;
                int cnt1 = (int)(u >> 60);
                unsigned e = (unsigned)u & 0x7FFu;
                float s1a = sgnapply(__ldg(&x1[ro0 + (e & 1023u)]), e);
                float s1b = sgnapply(__ldg(&x1[ro1 + (e & 1023u)]), e);
#pragma unroll
                for (int k = 1; k < 4; k++) {
                    if (k < cnt1) {
                        e = (unsigned)(u >> (11 * k)) & 0x7FFu;
                        s1a += sgnapply(__ldg(&x1[ro0 + (e & 1023u)]), e);
                        s1b += sgnapply(__ldg(&x1[ro1 + (e & 1023u)]), e);
                    }
                }
                // side 2
                u = rec.y;
                int cnt2 = (int)(u >> 60);
                e = (unsigned)u & 0x7FFu;
                float s2a = sgnapply(__ldg(&x2[ro0 + (e & 1023u)]), e);
                float s2b = sgnapply(__ldg(&x2[ro1 + (e & 1023u)]), e);
#pragma unroll
                for (int k = 1; k < 4; k++) {
                    if (k < cnt2) {
                        e = (unsigned)(u >> (11 * k)) & 0x7FFu;
                        s2a += sgnapply(__ldg(&x2[ro0 + (e & 1023u)]), e);
                        s2b += sgnapply(__ldg(&x2[ro1 + (e & 1023u)]), e);
                    }
                }
                sp[cl * TB + r]      = s1a * s2a;
                sp[cl * TB + r + 32] = s1b * s2b;
            }
        } else {
            // ---- fallback gather: CSR walk (round-7 path) ----
            int nw = Cn * TB;
            for (int p = tid; p < nw; p += NTHR) {
                int cl = p >> 6;
                int r  = p & 63;
                int c  = ck0 + cl;
                size_t rowoff = (size_t)(b0 + r) * DIM;

                float s1 = 0.0f;
                int e0 = __ldg(&g_cp1[c]), e1 = __ldg(&g_cp1[c + 1]);
                for (int e = e0; e < e1; e++) {
                    unsigned u = __ldg(&g_ent1[e]);
                    float x = __ldg(&x1[rowoff + (u & 1023u)]);
                    s1 += (u & 0x8000u) ? -x : x;
                }
                float s2 = 0.0f;
                int f0 = __ldg(&g_cp2[c]), f1 = __ldg(&g_cp2[c + 1]);
                for (int e = f0; e < f1; e++) {
                    unsigned u = __ldg(&g_ent2[e]);
                    float x = __ldg(&x2[rowoff + (u & 1023u)]);
                    s2 += (u & 0x8000u) ? -x : x;
                }
                sp[cl * TB + r] = s1 * s2;
            }
        }
        __syncthreads();

        // ---- GEMM over sub-chunks: stage 16 W rows to smem, then FFMA2 ----
        int nsub = (Cn + SUBCL - 1) / SUBCL;
        for (int sub = 0; sub < nsub; sub++) {
            {   // stage W: 16 rows x 512 floats = 8 floats per thread
                int row = tid >> 6;          // 0..15
                int col = (tid & 63) * 8;
                const float4* src = (const float4*)
                    &g_Wc[(size_t)(ck0 + sub * SUBCL + row) * OUT + col];
                float4 a = __ldg(src);
                float4 bfour = __ldg(src + 1);
                *(float4*)&WS[row * OUT + col]     = a;
                *(float4*)&WS[row * OUT + col + 4] = bfour;
            }
            __syncthreads();

            int base = sub * SUBCL;
            int Csub = min(SUBCL, Cn - base);
            if (Csub == SUBCL) {
#pragma unroll
                for (int c2 = 0; c2 < SUBCL; c2++) GEMM_STEP(sp, base, c2)
            } else {
                for (int c2 = 0; c2 < Csub; c2++) GEMM_STEP(sp, base, c2)
            }
            __syncthreads();
        }
    }

    // -------- LayerNorm: reduce each row across the 32 warps ---------------
    float* red_s = sp;                   // [64][33], aliases product tile
    float* red_q = sp + TB * 33;
#pragma unroll
    for (int p = 0; p < 2; p++) {
        float s = 0.0f, q = 0.0f;
#pragma unroll
        for (int k = 0; k < 8; k++) {
            float lo, hi;
            unpack2(acc2[p][k], lo, hi);
            s += lo + hi;
            q += lo * lo + hi * hi;
        }
        red_s[(r0 + p) * 33 + wrp] = s;
        red_q[(r0 + p) * 33 + wrp] = q;
    }
    __syncthreads();

    float* shmu = WS;                    // aliases W staging buffer
    float* shrs = WS + TB;
    if (tid < TB) {
        float s = 0.0f, q = 0.0f;
#pragma unroll
        for (int w = 0; w < 32; w++) {
            s += red_s[tid * 33 + w];
            q += red_q[tid * 33 + w];
        }
        float mu  = s * (1.0f / OUT);
        float var = q * (1.0f / OUT) - mu * mu;
        shmu[tid] = mu;
        shrs[tid] = rsqrtf(var + LN_EPS);
    }
    __syncthreads();

    // -------- normalize, affine, ReLU, store -------------------------------
#pragma unroll
    for (int p = 0; p < 2; p++) {
        int row = r0 + p;
        float mu = shmu[row];
        float rs = shrs[row];
        float* dst = out + (size_t)(b0 + row) * OUT + o0;
#pragma unroll
        for (int q = 0; q < 4; q++) {
            float4 g4 = __ldg((const float4*)(gamma + o0 + 4 * q));
            float4 e4 = __ldg((const float4*)(beta  + o0 + 4 * q));
            float lo0, hi0, lo1, hi1;
            unpack2(acc2[p][2 * q],     lo0, hi0);
            unpack2(acc2[p][2 * q + 1], lo1, hi1);
            float4 o4;
            o4.x = fmaxf((lo0 - mu) * rs * g4.x + e4.x, 0.0f);
            o4.y = fmaxf((hi0 - mu) * rs * g4.y + e4.y, 0.0f);
            o4.z = fmaxf((lo1 - mu) * rs * g4.z + e4.z, 0.0f);
            o4.w = fmaxf((hi1 - mu) * rs * g4.w + e4.w, 0.0f);
            *(float4*)(dst + 4 * q) = o4;
        }
    }
}

// ---------------------------------------------------------------------------
extern "C" void kernel_launch(void* const* d_in, const int* in_sizes, int n_in,
                              void* d_out, int out_size)
{
    const float* x1    = (const float*)d_in[0];
    const float* x2    = (const float*)d_in[1];
    const float* S1    = (const float*)d_in[2];
    const float* S2    = (const float*)d_in[3];
    const float* W     = (const float*)d_in[4];
    const float* b     = (const float*)d_in[5];
    const float* gamma = (const float*)d_in[6];
    const float* beta  = (const float*)d_in[7];
    float* out = (float*)d_out;

    // attribute set (not an allocation); idempotent and graph-legal
    cudaFuncSetAttribute(k_main, cudaFuncAttributeMaxDynamicSharedMemorySize,
                         DSM_BYTES);

    k_extract<<<2 * DIM, 256>>>(S1, S2);
    k_build<<<1, 1024>>>();
    k_wgather<<<MCAP, OUT>>>(W);
    k_main<<<BATCH / TB, NTHR, DSM_BYTES>>>(x1, x2, b, gamma, beta, out);
}